// round 16
// baseline (speedup 1.0000x reference)
#include <cuda_runtime.h>
#include <math.h>
#include <stdint.h>

#define F   256
#define NG  1024

// GEMM tile config (GH): BM=BN=64, BK=16, TM=TN=4, 256 threads
#define BM 64
#define BN 64
#define BK 16

#define GH_BX 16                  // 1024/64
#define GH_BY 12                  // 768/64
#define GH_BLOCKS (GH_BX * GH_BY) // 192

// ---------------- scratch ----------------
__device__ float g_wf[NG * F];
__device__ int   g_cnt[NG];
__device__ float g_x[NG * F];
__device__ float g_gi[NG * 3 * F];
__device__ float g_gh[NG * 3 * F];

// ---------------- f32x2 packed-math helpers ----------------
__device__ __forceinline__ uint64_t pack2(float x, float y) {
    uint64_t r; asm("mov.b64 %0, {%1, %2};" : "=l"(r) : "f"(x), "f"(y)); return r;
}
__device__ __forceinline__ uint64_t bcast2(float x) {
    uint64_t r; asm("mov.b64 %0, {%1, %1};" : "=l"(r) : "f"(x)); return r;
}
__device__ __forceinline__ void ffma2(uint64_t& d, uint64_t a, uint64_t b) {
    asm("fma.rn.f32x2 %0, %1, %2, %0;" : "+l"(d) : "l"(a), "l"(b));
}
__device__ __forceinline__ float2 unpack2(uint64_t v) {
    float2 f; asm("mov.b64 {%0, %1}, %2;" : "=f"(f.x), "=f"(f.y) : "l"(v)); return f;
}
__device__ __forceinline__ float fast_tanh(float x) {
    float r; asm("tanh.approx.f32 %0, %1;" : "=f"(r) : "f"(x)); return r;
}
__device__ __forceinline__ float4 ldcs4(const float4* p) {
    float4 v;
    asm("ld.global.cs.v4.f32 {%0,%1,%2,%3}, [%4];"
        : "=f"(v.x), "=f"(v.y), "=f"(v.z), "=f"(v.w) : "l"(p));
    return v;
}
__device__ __forceinline__ uint32_t smem_u32(const void* p) {
    uint32_t a;
    asm("{ .reg .u64 t; cvta.to.shared.u64 t, %1; cvt.u32.u64 %0, t; }"
        : "=r"(a) : "l"(p));
    return a;
}
__device__ __forceinline__ void cp16(uint32_t dst, const float* src) {
    asm volatile("cp.async.cg.shared.global [%0], [%1], 16;" :: "r"(dst), "l"(src));
}
#define CP_COMMIT() asm volatile("cp.async.commit_group;" ::: "memory")
#define CP_WAIT1()  asm volatile("cp.async.wait_group 1;" ::: "memory")
#define CP_WAIT0()  asm volatile("cp.async.wait_group 0;" ::: "memory")

// ---------------- shared memory layouts ----------------
struct SmemGemm {
    float As[2][BK][BM + 4];
    float Ws[2][BK][BN + 4];
};
struct SmemPool {
    float red[8];
    float c;
    float s[8];
    int   bnd[2];
    float acc[8][F];                      // 8 KB
    __align__(16) float st[8][2][2][F];   // 32 KB: warp x stage x node x dim
};
union SmemU { SmemGemm g; SmemPool p; };

// ---------------- GEMM body (256 threads, BM=BN=64): used by GH ----------------
template <int EPI>
__device__ __forceinline__ void gemm_body(
    SmemGemm& S,
    const float* __restrict__ A, const float* __restrict__ W,
    const float* __restrict__ bias, float* __restrict__ C,
    const int* __restrict__ cnt, int N, int K, int bx, int by)
{
    const int tid  = threadIdx.x;
    const int tx   = tid % (BN / 4);
    const int ty   = tid / (BN / 4);
    const int row0 = bx * BM;
    const int col0 = by * BN;

    float4 aR, wR;
    const int r_ld  = tid / (BK / 4);
    const int c4_ld = tid % (BK / 4);

    auto ldg = [&](int k0) {
        aR = *reinterpret_cast<const float4*>(A + (size_t)(row0 + r_ld) * K + k0 + c4_ld * 4);
        wR = *reinterpret_cast<const float4*>(W + (size_t)(col0 + r_ld) * K + k0 + c4_ld * 4);
    };
    auto sts = [&](int buf) {
        S.As[buf][c4_ld * 4 + 0][r_ld] = aR.x;
        S.As[buf][c4_ld * 4 + 1][r_ld] = aR.y;
        S.As[buf][c4_ld * 4 + 2][r_ld] = aR.z;
        S.As[buf][c4_ld * 4 + 3][r_ld] = aR.w;
        S.Ws[buf][c4_ld * 4 + 0][r_ld] = wR.x;
        S.Ws[buf][c4_ld * 4 + 1][r_ld] = wR.y;
        S.Ws[buf][c4_ld * 4 + 2][r_ld] = wR.z;
        S.Ws[buf][c4_ld * 4 + 3][r_ld] = wR.w;
    };

    uint64_t acc2[4][2];
    #pragma unroll
    for (int i = 0; i < 4; ++i) { acc2[i][0] = 0ull; acc2[i][1] = 0ull; }

    const int T = K / BK;
    ldg(0);
    sts(0);
    __syncthreads();

    for (int t = 0; t < T; ++t) {
        if (t + 1 < T) ldg((t + 1) * BK);
        const int buf = t & 1;
        #pragma unroll
        for (int kk = 0; kk < BK; ++kk) {
            float4 ra = *reinterpret_cast<const float4*>(&S.As[buf][kk][ty * 4]);
            float4 rw = *reinterpret_cast<const float4*>(&S.Ws[buf][kk][tx * 4]);
            uint64_t b01 = pack2(rw.x, rw.y);
            uint64_t b23 = pack2(rw.z, rw.w);
            uint64_t a0 = bcast2(ra.x), a1 = bcast2(ra.y);
            uint64_t a2 = bcast2(ra.z), a3 = bcast2(ra.w);
            ffma2(acc2[0][0], a0, b01); ffma2(acc2[0][1], a0, b23);
            ffma2(acc2[1][0], a1, b01); ffma2(acc2[1][1], a1, b23);
            ffma2(acc2[2][0], a2, b01); ffma2(acc2[2][1], a2, b23);
            ffma2(acc2[3][0], a3, b01); ffma2(acc2[3][1], a3, b23);
        }
        if (t + 1 < T) {
            sts((t + 1) & 1);
            __syncthreads();
        }
    }

    #pragma unroll
    for (int i = 0; i < 4; ++i) {
        int r = row0 + ty * 4 + i;
        int cz = (EPI == 1) ? cnt[r] : 1;
        #pragma unroll
        for (int j = 0; j < 2; ++j) {
            int col = col0 + tx * 4 + j * 2;
            float2 v = unpack2(acc2[i][j]);
            v.x += bias[col];
            v.y += bias[col + 1];
            if (EPI == 1) {
                v.x = v.x > 0.f ? v.x : expm1f(v.x);
                v.y = v.y > 0.f ? v.y : expm1f(v.y);
                if (cz == 0) { v.x = 0.f; v.y = 0.f; }
            }
            *reinterpret_cast<float2*>(C + (size_t)r * N + col) = v;
        }
    }
}

// ---------------- small GEMM body (128 threads, BM=32, BN=64, TM=TN=4) ------
template <int EPI>
__device__ __forceinline__ void gemm_body_128(
    const float* __restrict__ A, const float* __restrict__ W,
    const float* __restrict__ bias, float* __restrict__ C,
    const int* __restrict__ cnt, int N, int K, int bx, int by)
{
    __shared__ float As[2][16][36];
    __shared__ float Ws[2][16][68];

    const int tid  = threadIdx.x;        // 0..127
    const int tx   = tid & 15;
    const int ty   = tid >> 4;
    const int row0 = bx * 32;
    const int col0 = by * 64;

    const int lr  = tid >> 2;
    const int lc4 = tid & 3;

    float4 aR, wR0, wR1;
    auto ldg = [&](int k0) {
        aR  = *reinterpret_cast<const float4*>(A + (size_t)(row0 + lr) * K + k0 + lc4 * 4);
        wR0 = *reinterpret_cast<const float4*>(W + (size_t)(col0 + lr) * K + k0 + lc4 * 4);
        wR1 = *reinterpret_cast<const float4*>(W + (size_t)(col0 + 32 + lr) * K + k0 + lc4 * 4);
    };
    auto sts = [&](int buf) {
        As[buf][lc4 * 4 + 0][lr] = aR.x;
        As[buf][lc4 * 4 + 1][lr] = aR.y;
        As[buf][lc4 * 4 + 2][lr] = aR.z;
        As[buf][lc4 * 4 + 3][lr] = aR.w;
        Ws[buf][lc4 * 4 + 0][lr] = wR0.x;
        Ws[buf][lc4 * 4 + 1][lr] = wR0.y;
        Ws[buf][lc4 * 4 + 2][lr] = wR0.z;
        Ws[buf][lc4 * 4 + 3][lr] = wR0.w;
        Ws[buf][lc4 * 4 + 0][32 + lr] = wR1.x;
        Ws[buf][lc4 * 4 + 1][32 + lr] = wR1.y;
        Ws[buf][lc4 * 4 + 2][32 + lr] = wR1.z;
        Ws[buf][lc4 * 4 + 3][32 + lr] = wR1.w;
    };

    uint64_t acc2[4][2];
    #pragma unroll
    for (int i = 0; i < 4; ++i) { acc2[i][0] = 0ull; acc2[i][1] = 0ull; }

    const int T = K / 16;
    ldg(0); sts(0); __syncthreads();
    for (int t = 0; t < T; ++t) {
        if (t + 1 < T) ldg((t + 1) * 16);
        const int buf = t & 1;
        #pragma unroll
        for (int kk = 0; kk < 16; ++kk) {
            float4 ra = *reinterpret_cast<const float4*>(&As[buf][kk][ty * 4]);
            float4 rw = *reinterpret_cast<const float4*>(&Ws[buf][kk][tx * 4]);
            uint64_t b01 = pack2(rw.x, rw.y);
            uint64_t b23 = pack2(rw.z, rw.w);
            uint64_t a0 = bcast2(ra.x), a1 = bcast2(ra.y);
            uint64_t a2 = bcast2(ra.z), a3 = bcast2(ra.w);
            ffma2(acc2[0][0], a0, b01); ffma2(acc2[0][1], a0, b23);
            ffma2(acc2[1][0], a1, b01); ffma2(acc2[1][1], a1, b23);
            ffma2(acc2[2][0], a2, b01); ffma2(acc2[2][1], a2, b23);
            ffma2(acc2[3][0], a3, b01); ffma2(acc2[3][1], a3, b23);
        }
        if (t + 1 < T) { sts((t + 1) & 1); __syncthreads(); }
    }

    #pragma unroll
    for (int i = 0; i < 4; ++i) {
        int r = row0 + ty * 4 + i;
        int cz = (EPI == 1) ? cnt[r] : 1;
        #pragma unroll
        for (int j = 0; j < 2; ++j) {
            int col = col0 + tx * 4 + j * 2;
            float2 v = unpack2(acc2[i][j]);
            v.x += bias[col];
            v.y += bias[col + 1];
            if (EPI == 1) {
                v.x = v.x > 0.f ? v.x : expm1f(v.x);
                v.y = v.y > 0.f ? v.y : expm1f(v.y);
                if (cz == 0) { v.x = 0.f; v.y = 0.f; }
            }
            *reinterpret_cast<float2*>(C + (size_t)r * N + col) = v;
        }
    }
}

// ---------------- binary search (segment_ids sorted) ----------------
__device__ __forceinline__ int lbound(const int* __restrict__ seg, int n, int key) {
    int lo = 0, hi = n;
    while (lo < hi) {
        int mid = (lo + hi) >> 1;
        if (__ldg(seg + mid) < key) lo = mid + 1; else hi = mid;
    }
    return lo;
}

// ---------------- fused: GH GEMM blocks + pool blocks ----------------
// Pool v2: cp.async (LDGSTS) staging into per-warp smem double buffers.
// 2 stages x 2 nodes keep 4KB/warp in flight (same as the LDG champion),
// but the register file drops ~30 regs -> launch_bounds(256,4) -> 32 warps/SM.
__global__ void __launch_bounds__(256, 4) fused_pool_gh_kernel(
    const float* __restrict__ nf, const float* __restrict__ gf,
    const float* __restrict__ lw, const float* __restrict__ lb,
    const float* __restrict__ whh, const float* __restrict__ bhh,
    const int* __restrict__ seg, int n_nodes)
{
    __shared__ SmemU sm;

    if (blockIdx.x < GH_BLOCKS) {
        int bx = blockIdx.x % GH_BX;
        int by = blockIdx.x / GH_BX;
        gemm_body<0>(sm.g, gf, whh, bhh, g_gh, nullptr, 3 * F, F, bx, by);
        return;
    }

    const int g    = blockIdx.x - GH_BLOCKS;
    const int tid  = threadIdx.x;
    const int warp = tid >> 5;
    const int lane = tid & 31;

    // c_g = relu(g_feats[g]) . lw[0:256] + b
    {
        float v = fmaxf(gf[g * F + tid], 0.f) * lw[tid];
        #pragma unroll
        for (int o = 16; o; o >>= 1) v += __shfl_xor_sync(0xffffffffu, v, o);
        if (lane == 0) sm.p.red[warp] = v;
    }
    if (tid == 0)  sm.p.bnd[0] = lbound(seg, n_nodes, g);
    if (tid == 32) sm.p.bnd[1] = lbound(seg, n_nodes, g + 1);
    __syncthreads();
    if (tid == 0) {
        float c = lb[0];
        #pragma unroll
        for (int w = 0; w < 8; ++w) c += sm.p.red[w];
        sm.p.c = c;
    }
    __syncthreads();
    const float c     = sm.p.c;
    const int   start = sm.p.bnd[0];
    const int   end   = sm.p.bnd[1];

    // per-lane chunks of logit_w node half (coalesced mapping)
    float lwA[4], lwB[4];
    {
        float4 a = __ldg(reinterpret_cast<const float4*>(lw + F) + lane);
        float4 b = __ldg(reinterpret_cast<const float4*>(lw + F + 128) + lane);
        lwA[0]=a.x; lwA[1]=a.y; lwA[2]=a.z; lwA[3]=a.w;
        lwB[0]=b.x; lwB[1]=b.y; lwB[2]=b.z; lwB[3]=b.w;
    }

    float s = 0.f;
    float acc[8] = {0.f, 0.f, 0.f, 0.f, 0.f, 0.f, 0.f, 0.f};

    const int base = start + warp;
    const int span = end - base;
    // group g: nodes base+16g, base+16g+8 ; valid while second node < end
    const int G = (span >= 9) ? ((span - 9) / 16 + 1) : 0;

    const uint32_t st0 = smem_u32(&sm.p.st[warp][0][0][0]);

    // load group into buffer b (nodes n, n+8): lane stages its own 2x16B per node
    auto load_grp = [&](int b, int n) {
        const float* r0 = nf + (size_t)n * F + lane * 4;
        const float* r1 = nf + (size_t)(n + 8) * F + lane * 4;
        uint32_t d0 = st0 + (uint32_t)b * 2048u + lane * 16u;
        cp16(d0,        r0);
        cp16(d0 + 512,  r0 + 128);
        cp16(d0 + 1024, r1);
        cp16(d0 + 1536, r1 + 128);
        CP_COMMIT();
    };
    // compute on buffer b (2 nodes); lane reads exactly what it staged
    auto compute_grp = [&](int b) {
        const float4* q = reinterpret_cast<const float4*>(&sm.p.st[warp][b][0][0]) + lane;
        float4 a0 = q[0],  a1 = q[32];
        float4 b0 = q[64], b1 = q[96];
        float q1 = a0.x * lwA[0], q2 = b0.x * lwA[0];
        q1 = fmaf(a0.y, lwA[1], q1); q2 = fmaf(b0.y, lwA[1], q2);
        q1 = fmaf(a0.z, lwA[2], q1); q2 = fmaf(b0.z, lwA[2], q2);
        q1 = fmaf(a0.w, lwA[3], q1); q2 = fmaf(b0.w, lwA[3], q2);
        q1 = fmaf(a1.x, lwB[0], q1); q2 = fmaf(b1.x, lwB[0], q2);
        q1 = fmaf(a1.y, lwB[1], q1); q2 = fmaf(b1.y, lwB[1], q2);
        q1 = fmaf(a1.z, lwB[2], q1); q2 = fmaf(b1.z, lwB[2], q2);
        q1 = fmaf(a1.w, lwB[3], q1); q2 = fmaf(b1.w, lwB[3], q2);
        #pragma unroll
        for (int o = 16; o; o >>= 1) {
            q1 += __shfl_xor_sync(0xffffffffu, q1, o);
            q2 += __shfl_xor_sync(0xffffffffu, q2, o);
        }
        float t1 = c + q1, t2 = c + q2;
        float z1 = t1 > 0.f ? t1 : 0.01f * t1;
        float z2 = t2 > 0.f ? t2 : 0.01f * t2;
        float e1 = __expf(z1), e2 = __expf(z2);
        s += e1 + e2;
        acc[0] = fmaf(e1, a0.x, fmaf(e2, b0.x, acc[0]));
        acc[1] = fmaf(e1, a0.y, fmaf(e2, b0.y, acc[1]));
        acc[2] = fmaf(e1, a0.z, fmaf(e2, b0.z, acc[2]));
        acc[3] = fmaf(e1, a0.w, fmaf(e2, b0.w, acc[3]));
        acc[4] = fmaf(e1, a1.x, fmaf(e2, b1.x, acc[4]));
        acc[5] = fmaf(e1, a1.y, fmaf(e2, b1.y, acc[5]));
        acc[6] = fmaf(e1, a1.z, fmaf(e2, b1.z, acc[6]));
        acc[7] = fmaf(e1, a1.w, fmaf(e2, b1.w, acc[7]));
    };

    if (G > 0) {
        load_grp(0, base);
        if (G > 1) load_grp(1, base + 16);
        for (int gg = 0; gg < G; ++gg) {
            if (gg < G - 1) { CP_WAIT1(); } else { CP_WAIT0(); }
            compute_grp(gg & 1);
            if (gg + 2 < G) load_grp(gg & 1, base + 16 * (gg + 2));
        }
    }

    // ---- tail: remaining warp-nodes (step 8), plain streaming LDG ----
    for (int n = base + 16 * G; n < end; n += 8) {
        const float4* p = reinterpret_cast<const float4*>(nf + (size_t)n * F) + lane;
        float4 f0 = ldcs4(p), f1 = ldcs4(p + 32);
        float d = f0.x * lwA[0];
        d = fmaf(f0.y, lwA[1], d); d = fmaf(f0.z, lwA[2], d); d = fmaf(f0.w, lwA[3], d);
        d = fmaf(f1.x, lwB[0], d); d = fmaf(f1.y, lwB[1], d);
        d = fmaf(f1.z, lwB[2], d); d = fmaf(f1.w, lwB[3], d);
        #pragma unroll
        for (int o = 16; o; o >>= 1) d += __shfl_xor_sync(0xffffffffu, d, o);
        float t  = c + d;
        float z  = t > 0.f ? t : 0.01f * t;
        float e  = __expf(z);
        s += e;
        acc[0] = fmaf(e, f0.x, acc[0]);
        acc[1] = fmaf(e, f0.y, acc[1]);
        acc[2] = fmaf(e, f0.z, acc[2]);
        acc[3] = fmaf(e, f0.w, acc[3]);
        acc[4] = fmaf(e, f1.x, acc[4]);
        acc[5] = fmaf(e, f1.y, acc[5]);
        acc[6] = fmaf(e, f1.z, acc[6]);
        acc[7] = fmaf(e, f1.w, acc[7]);
    }

    if (lane == 0) sm.p.s[warp] = s;
    #pragma unroll
    for (int j = 0; j < 4; ++j) {
        sm.p.acc[warp][lane * 4 + j]       = acc[j];
        sm.p.acc[warp][128 + lane * 4 + j] = acc[4 + j];
    }
    __syncthreads();

    float S = 0.f, val = 0.f;
    #pragma unroll
    for (int w = 0; w < 8; ++w) {
        S   += sm.p.s[w];
        val += sm.p.acc[w][tid];
    }
    g_wf[g * F + tid] = (S > 0.f) ? val / S : 0.f;
    if (tid == 0) g_cnt[g] = end - start;
}

// proj: x = elu(wf @ proj_w.T + proj_b), zeroed for empty graphs
__global__ void __launch_bounds__(128) proj_kernel(
    const float* __restrict__ pw, const float* __restrict__ pb)
{
    gemm_body_128<1>(g_wf, pw, pb, g_x, g_cnt, F, F, blockIdx.x, blockIdx.y);
}

// GI = x @ w_ih.T + b_ih  (384 blocks x 128 threads)
__global__ void __launch_bounds__(128) gi_kernel(
    const float* __restrict__ wih, const float* __restrict__ bih)
{
    gemm_body_128<0>(g_x, wih, bih, g_gi, nullptr, 3 * F, F, blockIdx.x, blockIdx.y);
}

// ---------------- GRU elementwise (float2, 512 blocks) ----------------
__global__ void __launch_bounds__(256) gru_kernel(
    const float* __restrict__ gf, float* __restrict__ out)
{
    int idx2 = blockIdx.x * blockDim.x + threadIdx.x;
    if (idx2 >= NG * F / 2) return;
    int g  = idx2 / (F / 2);
    int d2 = (idx2 % (F / 2)) * 2;
    const float* gi = g_gi + (size_t)g * 3 * F;
    const float* gh = g_gh + (size_t)g * 3 * F;

    float2 ir  = *reinterpret_cast<const float2*>(gi + d2);
    float2 iz  = *reinterpret_cast<const float2*>(gi + F + d2);
    float2 inn = *reinterpret_cast<const float2*>(gi + 2 * F + d2);
    float2 hr  = *reinterpret_cast<const float2*>(gh + d2);
    float2 hz  = *reinterpret_cast<const float2*>(gh + F + d2);
    float2 hn  = *reinterpret_cast<const float2*>(gh + 2 * F + d2);
    float2 h   = *reinterpret_cast<const float2*>(gf + (size_t)g * F + d2);

    float2 o;
    {
        float r = 0.5f * fast_tanh(0.5f * (ir.x + hr.x)) + 0.5f;
        float z = 0.5f * fast_tanh(0.5f * (iz.x + hz.x)) + 0.5f;
        float nn = fast_tanh(fmaf(r, hn.x, inn.x));
        o.x = fmaf(1.f - z, nn, z * h.x);
    }
    {
        float r = 0.5f * fast_tanh(0.5f * (ir.y + hr.y)) + 0.5f;
        float z = 0.5f * fast_tanh(0.5f * (iz.y + hz.y)) + 0.5f;
        float nn = fast_tanh(fmaf(r, hn.y, inn.y));
        o.y = fmaf(1.f - z, nn, z * h.y);
    }
    *reinterpret_cast<float2*>(out + (size_t)g * F + d2) = o;
}

// ---------------- launch ----------------
extern "C" void kernel_launch(void* const* d_in, const int* in_sizes, int n_in,
                              void* d_out, int out_size)
{
    int o = (n_in >= 12) ? 1 : 0;
    const float* nf  = (const float*)d_in[0];
    const float* gf  = (const float*)d_in[1];
    const int*   seg = (const int*)  d_in[2];
    const float* lw  = (const float*)d_in[3 + o];
    const float* lb  = (const float*)d_in[4 + o];
    const float* pw  = (const float*)d_in[5 + o];
    const float* pb  = (const float*)d_in[6 + o];
    const float* wih = (const float*)d_in[7 + o];
    const float* whh = (const float*)d_in[8 + o];
    const float* bih = (const float*)d_in[9 + o];
    const float* bhh = (const float*)d_in[10 + o];
    float* out = (float*)d_out;
    int n_nodes = in_sizes[0] / F;

    fused_pool_gh_kernel<<<GH_BLOCKS + NG, 256>>>(nf, gf, lw, lb, whh, bhh, seg, n_nodes);
    proj_kernel<<<dim3(NG / 32, F / 64), 128>>>(pw, pb);
    gi_kernel<<<dim3(NG / 32, (3 * F) / 64), 128>>>(wih, bih);
    gru_kernel<<<(NG * F / 2 + 255) / 256, 256>>>(gf, out);
}

// round 17
// speedup vs baseline: 1.0715x; 1.0715x over previous
#include <cuda_runtime.h>
#include <math.h>
#include <stdint.h>

#define F   256
#define NG  1024

// GEMM tile config (GH): BM=BN=64, BK=16, TM=TN=4, 256 threads
#define BM 64
#define BN 64
#define BK 16

#define GH_BX 16                  // 1024/64
#define GH_BY 12                  // 768/64
#define GH_BLOCKS (GH_BX * GH_BY) // 192

// ---------------- scratch ----------------
__device__ float g_wf[NG * F];
__device__ int   g_cnt[NG];
__device__ float g_x[NG * F];
__device__ float g_gh[NG * 3 * F];

// ---------------- f32x2 packed-math helpers ----------------
__device__ __forceinline__ uint64_t pack2(float x, float y) {
    uint64_t r; asm("mov.b64 %0, {%1, %2};" : "=l"(r) : "f"(x), "f"(y)); return r;
}
__device__ __forceinline__ uint64_t bcast2(float x) {
    uint64_t r; asm("mov.b64 %0, {%1, %1};" : "=l"(r) : "f"(x)); return r;
}
__device__ __forceinline__ void ffma2(uint64_t& d, uint64_t a, uint64_t b) {
    asm("fma.rn.f32x2 %0, %1, %2, %0;" : "+l"(d) : "l"(a), "l"(b));
}
__device__ __forceinline__ float2 unpack2(uint64_t v) {
    float2 f; asm("mov.b64 {%0, %1}, %2;" : "=f"(f.x), "=f"(f.y) : "l"(v)); return f;
}
__device__ __forceinline__ float fast_tanh(float x) {
    float r; asm("tanh.approx.f32 %0, %1;" : "=f"(r) : "f"(x)); return r;
}
__device__ __forceinline__ float4 ldcs4(const float4* p) {
    float4 v;
    asm("ld.global.cs.v4.f32 {%0,%1,%2,%3}, [%4];"
        : "=f"(v.x), "=f"(v.y), "=f"(v.z), "=f"(v.w) : "l"(p));
    return v;
}

// ---------------- shared memory layouts ----------------
struct SmemGemm {
    float As[2][BK][BM + 4];
    float Ws[2][BK][BN + 4];
};
struct SmemPool {
    float red[8];
    float c;
    float s[8];
    int   bnd[2];
    float acc[8][F];
};
union SmemU { SmemGemm g; SmemPool p; };

// ---------------- GEMM body (256 threads, BM=BN=64): used by GH ----------------
template <int EPI>
__device__ __forceinline__ void gemm_body(
    SmemGemm& S,
    const float* __restrict__ A, const float* __restrict__ W,
    const float* __restrict__ bias, float* __restrict__ C,
    const int* __restrict__ cnt, int N, int K, int bx, int by)
{
    const int tid  = threadIdx.x;
    const int tx   = tid % (BN / 4);
    const int ty   = tid / (BN / 4);
    const int row0 = bx * BM;
    const int col0 = by * BN;

    float4 aR, wR;
    const int r_ld  = tid / (BK / 4);
    const int c4_ld = tid % (BK / 4);

    auto ldg = [&](int k0) {
        aR = *reinterpret_cast<const float4*>(A + (size_t)(row0 + r_ld) * K + k0 + c4_ld * 4);
        wR = *reinterpret_cast<const float4*>(W + (size_t)(col0 + r_ld) * K + k0 + c4_ld * 4);
    };
    auto sts = [&](int buf) {
        S.As[buf][c4_ld * 4 + 0][r_ld] = aR.x;
        S.As[buf][c4_ld * 4 + 1][r_ld] = aR.y;
        S.As[buf][c4_ld * 4 + 2][r_ld] = aR.z;
        S.As[buf][c4_ld * 4 + 3][r_ld] = aR.w;
        S.Ws[buf][c4_ld * 4 + 0][r_ld] = wR.x;
        S.Ws[buf][c4_ld * 4 + 1][r_ld] = wR.y;
        S.Ws[buf][c4_ld * 4 + 2][r_ld] = wR.z;
        S.Ws[buf][c4_ld * 4 + 3][r_ld] = wR.w;
    };

    uint64_t acc2[4][2];
    #pragma unroll
    for (int i = 0; i < 4; ++i) { acc2[i][0] = 0ull; acc2[i][1] = 0ull; }

    const int T = K / BK;
    ldg(0);
    sts(0);
    __syncthreads();

    for (int t = 0; t < T; ++t) {
        if (t + 1 < T) ldg((t + 1) * BK);
        const int buf = t & 1;
        #pragma unroll
        for (int kk = 0; kk < BK; ++kk) {
            float4 ra = *reinterpret_cast<const float4*>(&S.As[buf][kk][ty * 4]);
            float4 rw = *reinterpret_cast<const float4*>(&S.Ws[buf][kk][tx * 4]);
            uint64_t b01 = pack2(rw.x, rw.y);
            uint64_t b23 = pack2(rw.z, rw.w);
            uint64_t a0 = bcast2(ra.x), a1 = bcast2(ra.y);
            uint64_t a2 = bcast2(ra.z), a3 = bcast2(ra.w);
            ffma2(acc2[0][0], a0, b01); ffma2(acc2[0][1], a0, b23);
            ffma2(acc2[1][0], a1, b01); ffma2(acc2[1][1], a1, b23);
            ffma2(acc2[2][0], a2, b01); ffma2(acc2[2][1], a2, b23);
            ffma2(acc2[3][0], a3, b01); ffma2(acc2[3][1], a3, b23);
        }
        if (t + 1 < T) {
            sts((t + 1) & 1);
            __syncthreads();
        }
    }

    #pragma unroll
    for (int i = 0; i < 4; ++i) {
        int r = row0 + ty * 4 + i;
        int cz = (EPI == 1) ? cnt[r] : 1;
        #pragma unroll
        for (int j = 0; j < 2; ++j) {
            int col = col0 + tx * 4 + j * 2;
            float2 v = unpack2(acc2[i][j]);
            v.x += bias[col];
            v.y += bias[col + 1];
            if (EPI == 1) {
                v.x = v.x > 0.f ? v.x : expm1f(v.x);
                v.y = v.y > 0.f ? v.y : expm1f(v.y);
                if (cz == 0) { v.x = 0.f; v.y = 0.f; }
            }
            *reinterpret_cast<float2*>(C + (size_t)r * N + col) = v;
        }
    }
}

// ---------------- small GEMM body (128 threads, BM=32, BN=64, TM=TN=4) ------
template <int EPI>
__device__ __forceinline__ void gemm_body_128(
    const float* __restrict__ A, const float* __restrict__ W,
    const float* __restrict__ bias, float* __restrict__ C,
    const int* __restrict__ cnt, int N, int K, int bx, int by)
{
    __shared__ float As[2][16][36];
    __shared__ float Ws[2][16][68];

    const int tid  = threadIdx.x;        // 0..127
    const int tx   = tid & 15;
    const int ty   = tid >> 4;
    const int row0 = bx * 32;
    const int col0 = by * 64;

    const int lr  = tid >> 2;
    const int lc4 = tid & 3;

    float4 aR, wR0, wR1;
    auto ldg = [&](int k0) {
        aR  = *reinterpret_cast<const float4*>(A + (size_t)(row0 + lr) * K + k0 + lc4 * 4);
        wR0 = *reinterpret_cast<const float4*>(W + (size_t)(col0 + lr) * K + k0 + lc4 * 4);
        wR1 = *reinterpret_cast<const float4*>(W + (size_t)(col0 + 32 + lr) * K + k0 + lc4 * 4);
    };
    auto sts = [&](int buf) {
        As[buf][lc4 * 4 + 0][lr] = aR.x;
        As[buf][lc4 * 4 + 1][lr] = aR.y;
        As[buf][lc4 * 4 + 2][lr] = aR.z;
        As[buf][lc4 * 4 + 3][lr] = aR.w;
        Ws[buf][lc4 * 4 + 0][lr] = wR0.x;
        Ws[buf][lc4 * 4 + 1][lr] = wR0.y;
        Ws[buf][lc4 * 4 + 2][lr] = wR0.z;
        Ws[buf][lc4 * 4 + 3][lr] = wR0.w;
        Ws[buf][lc4 * 4 + 0][32 + lr] = wR1.x;
        Ws[buf][lc4 * 4 + 1][32 + lr] = wR1.y;
        Ws[buf][lc4 * 4 + 2][32 + lr] = wR1.z;
        Ws[buf][lc4 * 4 + 3][32 + lr] = wR1.w;
    };

    uint64_t acc2[4][2];
    #pragma unroll
    for (int i = 0; i < 4; ++i) { acc2[i][0] = 0ull; acc2[i][1] = 0ull; }

    const int T = K / 16;
    ldg(0); sts(0); __syncthreads();
    for (int t = 0; t < T; ++t) {
        if (t + 1 < T) ldg((t + 1) * 16);
        const int buf = t & 1;
        #pragma unroll
        for (int kk = 0; kk < 16; ++kk) {
            float4 ra = *reinterpret_cast<const float4*>(&As[buf][kk][ty * 4]);
            float4 rw = *reinterpret_cast<const float4*>(&Ws[buf][kk][tx * 4]);
            uint64_t b01 = pack2(rw.x, rw.y);
            uint64_t b23 = pack2(rw.z, rw.w);
            uint64_t a0 = bcast2(ra.x), a1 = bcast2(ra.y);
            uint64_t a2 = bcast2(ra.z), a3 = bcast2(ra.w);
            ffma2(acc2[0][0], a0, b01); ffma2(acc2[0][1], a0, b23);
            ffma2(acc2[1][0], a1, b01); ffma2(acc2[1][1], a1, b23);
            ffma2(acc2[2][0], a2, b01); ffma2(acc2[2][1], a2, b23);
            ffma2(acc2[3][0], a3, b01); ffma2(acc2[3][1], a3, b23);
        }
        if (t + 1 < T) { sts((t + 1) & 1); __syncthreads(); }
    }

    #pragma unroll
    for (int i = 0; i < 4; ++i) {
        int r = row0 + ty * 4 + i;
        int cz = (EPI == 1) ? cnt[r] : 1;
        #pragma unroll
        for (int j = 0; j < 2; ++j) {
            int col = col0 + tx * 4 + j * 2;
            float2 v = unpack2(acc2[i][j]);
            v.x += bias[col];
            v.y += bias[col + 1];
            if (EPI == 1) {
                v.x = v.x > 0.f ? v.x : expm1f(v.x);
                v.y = v.y > 0.f ? v.y : expm1f(v.y);
                if (cz == 0) { v.x = 0.f; v.y = 0.f; }
            }
            *reinterpret_cast<float2*>(C + (size_t)r * N + col) = v;
        }
    }
}

// ---------------- binary search (segment_ids sorted) ----------------
__device__ __forceinline__ int lbound(const int* __restrict__ seg, int n, int key) {
    int lo = 0, hi = n;
    while (lo < hi) {
        int mid = (lo + hi) >> 1;
        if (__ldg(seg + mid) < key) lo = mid + 1; else hi = mid;
    }
    return lo;
}

// ---------------- fused: GH GEMM blocks + pool blocks ----------------
// Pool: unnormalized exp accumulation, coalesced lanes, unroll-4 with 8
// front-batched contiguous LDG.128, plain fmaf math, launch_bounds(256,3).
// Verified local optimum (59.3us @ DRAM 58.8%). Do not modify.
__global__ void __launch_bounds__(256, 3) fused_pool_gh_kernel(
    const float* __restrict__ nf, const float* __restrict__ gf,
    const float* __restrict__ lw, const float* __restrict__ lb,
    const float* __restrict__ whh, const float* __restrict__ bhh,
    const int* __restrict__ seg, int n_nodes)
{
    __shared__ SmemU sm;

    if (blockIdx.x < GH_BLOCKS) {
        int bx = blockIdx.x % GH_BX;
        int by = blockIdx.x / GH_BX;
        gemm_body<0>(sm.g, gf, whh, bhh, g_gh, nullptr, 3 * F, F, bx, by);
        return;
    }

    const int g    = blockIdx.x - GH_BLOCKS;
    const int tid  = threadIdx.x;
    const int warp = tid >> 5;
    const int lane = tid & 31;

    // c_g = relu(g_feats[g]) . lw[0:256] + b
    {
        float v = fmaxf(gf[g * F + tid], 0.f) * lw[tid];
        #pragma unroll
        for (int o = 16; o; o >>= 1) v += __shfl_xor_sync(0xffffffffu, v, o);
        if (lane == 0) sm.p.red[warp] = v;
    }
    if (tid == 0)  sm.p.bnd[0] = lbound(seg, n_nodes, g);
    if (tid == 32) sm.p.bnd[1] = lbound(seg, n_nodes, g + 1);
    __syncthreads();
    if (tid == 0) {
        float c = lb[0];
        #pragma unroll
        for (int w = 0; w < 8; ++w) c += sm.p.red[w];
        sm.p.c = c;
    }
    __syncthreads();
    const float c     = sm.p.c;
    const int   start = sm.p.bnd[0];
    const int   end   = sm.p.bnd[1];

    // per-lane chunks of logit_w node half (coalesced mapping)
    float lwA[4], lwB[4];
    {
        float4 a = __ldg(reinterpret_cast<const float4*>(lw + F) + lane);
        float4 b = __ldg(reinterpret_cast<const float4*>(lw + F + 128) + lane);
        lwA[0]=a.x; lwA[1]=a.y; lwA[2]=a.z; lwA[3]=a.w;
        lwB[0]=b.x; lwB[1]=b.y; lwB[2]=b.z; lwB[3]=b.w;
    }

    float s = 0.f;
    float acc[8] = {0.f, 0.f, 0.f, 0.f, 0.f, 0.f, 0.f, 0.f};

    int n = start + warp;
    // ---- main loop: 4 nodes per iteration, 8 front-batched contiguous LDG.128 ----
    for (; n + 24 < end; n += 32) {
        const float4* p = reinterpret_cast<const float4*>(nf + (size_t)n * F) + lane;
        float4 a0 = ldcs4(p),        a1 = ldcs4(p + 32);
        float4 b0 = ldcs4(p + 512),  b1 = ldcs4(p + 544);
        float4 c0 = ldcs4(p + 1024), c1 = ldcs4(p + 1056);
        float4 d0 = ldcs4(p + 1536), d1 = ldcs4(p + 1568);

        float q1 = a0.x * lwA[0], q2 = b0.x * lwA[0];
        float q3 = c0.x * lwA[0], q4 = d0.x * lwA[0];
        q1 = fmaf(a0.y, lwA[1], q1); q2 = fmaf(b0.y, lwA[1], q2);
        q3 = fmaf(c0.y, lwA[1], q3); q4 = fmaf(d0.y, lwA[1], q4);
        q1 = fmaf(a0.z, lwA[2], q1); q2 = fmaf(b0.z, lwA[2], q2);
        q3 = fmaf(c0.z, lwA[2], q3); q4 = fmaf(d0.z, lwA[2], q4);
        q1 = fmaf(a0.w, lwA[3], q1); q2 = fmaf(b0.w, lwA[3], q2);
        q3 = fmaf(c0.w, lwA[3], q3); q4 = fmaf(d0.w, lwA[3], q4);
        q1 = fmaf(a1.x, lwB[0], q1); q2 = fmaf(b1.x, lwB[0], q2);
        q3 = fmaf(c1.x, lwB[0], q3); q4 = fmaf(d1.x, lwB[0], q4);
        q1 = fmaf(a1.y, lwB[1], q1); q2 = fmaf(b1.y, lwB[1], q2);
        q3 = fmaf(c1.y, lwB[1], q3); q4 = fmaf(d1.y, lwB[1], q4);
        q1 = fmaf(a1.z, lwB[2], q1); q2 = fmaf(b1.z, lwB[2], q2);
        q3 = fmaf(c1.z, lwB[2], q3); q4 = fmaf(d1.z, lwB[2], q4);
        q1 = fmaf(a1.w, lwB[3], q1); q2 = fmaf(b1.w, lwB[3], q2);
        q3 = fmaf(c1.w, lwB[3], q3); q4 = fmaf(d1.w, lwB[3], q4);
        #pragma unroll
        for (int o = 16; o; o >>= 1) {
            q1 += __shfl_xor_sync(0xffffffffu, q1, o);
            q2 += __shfl_xor_sync(0xffffffffu, q2, o);
            q3 += __shfl_xor_sync(0xffffffffu, q3, o);
            q4 += __shfl_xor_sync(0xffffffffu, q4, o);
        }
        float t1 = c + q1, t2 = c + q2, t3 = c + q3, t4 = c + q4;
        float z1 = t1 > 0.f ? t1 : 0.01f * t1;
        float z2 = t2 > 0.f ? t2 : 0.01f * t2;
        float z3 = t3 > 0.f ? t3 : 0.01f * t3;
        float z4 = t4 > 0.f ? t4 : 0.01f * t4;
        float e1 = __expf(z1), e2 = __expf(z2);
        float e3 = __expf(z3), e4 = __expf(z4);
        s += (e1 + e2) + (e3 + e4);
        acc[0] = fmaf(e1, a0.x, fmaf(e2, b0.x, fmaf(e3, c0.x, fmaf(e4, d0.x, acc[0]))));
        acc[1] = fmaf(e1, a0.y, fmaf(e2, b0.y, fmaf(e3, c0.y, fmaf(e4, d0.y, acc[1]))));
        acc[2] = fmaf(e1, a0.z, fmaf(e2, b0.z, fmaf(e3, c0.z, fmaf(e4, d0.z, acc[2]))));
        acc[3] = fmaf(e1, a0.w, fmaf(e2, b0.w, fmaf(e3, c0.w, fmaf(e4, d0.w, acc[3]))));
        acc[4] = fmaf(e1, a1.x, fmaf(e2, b1.x, fmaf(e3, c1.x, fmaf(e4, d1.x, acc[4]))));
        acc[5] = fmaf(e1, a1.y, fmaf(e2, b1.y, fmaf(e3, c1.y, fmaf(e4, d1.y, acc[5]))));
        acc[6] = fmaf(e1, a1.z, fmaf(e2, b1.z, fmaf(e3, c1.z, fmaf(e4, d1.z, acc[6]))));
        acc[7] = fmaf(e1, a1.w, fmaf(e2, b1.w, fmaf(e3, c1.w, fmaf(e4, d1.w, acc[7]))));
    }
    // ---- tail: up to 3 nodes per warp ----
    for (; n < end; n += 8) {
        const float4* p = reinterpret_cast<const float4*>(nf + (size_t)n * F) + lane;
        float4 f0 = ldcs4(p), f1 = ldcs4(p + 32);
        float d = f0.x * lwA[0];
        d = fmaf(f0.y, lwA[1], d); d = fmaf(f0.z, lwA[2], d); d = fmaf(f0.w, lwA[3], d);
        d = fmaf(f1.x, lwB[0], d); d = fmaf(f1.y, lwB[1], d);
        d = fmaf(f1.z, lwB[2], d); d = fmaf(f1.w, lwB[3], d);
        #pragma unroll
        for (int o = 16; o; o >>= 1) d += __shfl_xor_sync(0xffffffffu, d, o);
        float t  = c + d;
        float z  = t > 0.f ? t : 0.01f * t;
        float e  = __expf(z);
        s += e;
        acc[0] = fmaf(e, f0.x, acc[0]);
        acc[1] = fmaf(e, f0.y, acc[1]);
        acc[2] = fmaf(e, f0.z, acc[2]);
        acc[3] = fmaf(e, f0.w, acc[3]);
        acc[4] = fmaf(e, f1.x, acc[4]);
        acc[5] = fmaf(e, f1.y, acc[5]);
        acc[6] = fmaf(e, f1.z, acc[6]);
        acc[7] = fmaf(e, f1.w, acc[7]);
    }

    if (lane == 0) sm.p.s[warp] = s;
    #pragma unroll
    for (int j = 0; j < 4; ++j) {
        sm.p.acc[warp][lane * 4 + j]       = acc[j];
        sm.p.acc[warp][128 + lane * 4 + j] = acc[4 + j];
    }
    __syncthreads();

    float S = 0.f, val = 0.f;
    #pragma unroll
    for (int w = 0; w < 8; ++w) {
        S   += sm.p.s[w];
        val += sm.p.acc[w][tid];
    }
    g_wf[g * F + tid] = (S > 0.f) ? val / S : 0.f;
    if (tid == 0) g_cnt[g] = end - start;
}

// proj: x = elu(wf @ proj_w.T + proj_b), zeroed for empty graphs
__global__ void __launch_bounds__(128) proj_kernel(
    const float* __restrict__ pw, const float* __restrict__ pb)
{
    gemm_body_128<1>(g_wf, pw, pb, g_x, g_cnt, F, F, blockIdx.x, blockIdx.y);
}

// ---------------- fused GI GEMM (all 3 gates) + GRU epilogue ----------------
// Block: 16 rows x 64 dims x 3 gates, K=256, 128 threads.
// Grid (64, 4) = 256 blocks. Per kk: 1 LDS.64 (A) + 3 LDS.128 (W) vs 12 FFMA2.
// Epilogue computes the full GRU from the in-register GI gates + g_gh/gf.
__global__ void __launch_bounds__(128) gigru_kernel(
    const float* __restrict__ gf,
    const float* __restrict__ wih, const float* __restrict__ bih,
    float* __restrict__ out)
{
    __shared__ float As[2][16][20];     // 16 rows
    __shared__ float Ws[2][16][208];    // 3 gates x 64 cols (stride 68)

    const int tid  = threadIdx.x;       // 0..127
    const int tx   = tid & 15;          // 4 dims
    const int ty   = tid >> 4;          // 0..7, 2 rows each
    const int row0 = blockIdx.x * 16;
    const int colg = blockIdx.y * 64;

    float4 aR;                          // tid<64 loads A
    float4 wR[6];
    auto ldg = [&](int k0) {
        if (tid < 64) {
            int lr  = tid >> 2;         // 0..15
            int lc4 = tid & 3;
            aR = *reinterpret_cast<const float4*>(g_x + (size_t)(row0 + lr) * F + k0 + lc4 * 4);
        }
        #pragma unroll
        for (int i = 0; i < 6; ++i) {
            int flat = tid + i * 128;   // 0..767
            int wrow = flat >> 2;       // 0..191
            int wc4  = flat & 3;
            int gate = wrow >> 6;
            int wcol = wrow & 63;
            wR[i] = *reinterpret_cast<const float4*>(
                wih + (size_t)(gate * F + colg + wcol) * F + k0 + wc4 * 4);
        }
    };
    auto sts = [&](int buf) {
        if (tid < 64) {
            int lr  = tid >> 2;
            int lc4 = tid & 3;
            As[buf][lc4 * 4 + 0][lr] = aR.x;
            As[buf][lc4 * 4 + 1][lr] = aR.y;
            As[buf][lc4 * 4 + 2][lr] = aR.z;
            As[buf][lc4 * 4 + 3][lr] = aR.w;
        }
        #pragma unroll
        for (int i = 0; i < 6; ++i) {
            int flat = tid + i * 128;
            int wrow = flat >> 2;
            int wc4  = flat & 3;
            int gate = wrow >> 6;
            int wcol = wrow & 63;
            Ws[buf][wc4 * 4 + 0][gate * 68 + wcol] = wR[i].x;
            Ws[buf][wc4 * 4 + 1][gate * 68 + wcol] = wR[i].y;
            Ws[buf][wc4 * 4 + 2][gate * 68 + wcol] = wR[i].z;
            Ws[buf][wc4 * 4 + 3][gate * 68 + wcol] = wR[i].w;
        }
    };

    // acc[gate][row(2)][dimpair(2)]
    uint64_t acc[3][2][2];
    #pragma unroll
    for (int gg = 0; gg < 3; ++gg)
        #pragma unroll
        for (int i = 0; i < 2; ++i) { acc[gg][i][0] = 0ull; acc[gg][i][1] = 0ull; }

    ldg(0); sts(0); __syncthreads();
    for (int t = 0; t < 16; ++t) {
        if (t + 1 < 16) ldg((t + 1) * 16);
        const int buf = t & 1;
        #pragma unroll
        for (int kk = 0; kk < 16; ++kk) {
            float2 ra = *reinterpret_cast<const float2*>(&As[buf][kk][ty * 2]);
            uint64_t a0 = bcast2(ra.x), a1 = bcast2(ra.y);
            #pragma unroll
            for (int gg = 0; gg < 3; ++gg) {
                float4 rw = *reinterpret_cast<const float4*>(&Ws[buf][kk][gg * 68 + tx * 4]);
                uint64_t b01 = pack2(rw.x, rw.y);
                uint64_t b23 = pack2(rw.z, rw.w);
                ffma2(acc[gg][0][0], a0, b01); ffma2(acc[gg][0][1], a0, b23);
                ffma2(acc[gg][1][0], a1, b01); ffma2(acc[gg][1][1], a1, b23);
            }
        }
        if (t + 1 < 16) { sts((t + 1) & 1); __syncthreads(); }
    }

    // ---- GRU epilogue ----
    const int cc = colg + tx * 4;
    float4 bir = *reinterpret_cast<const float4*>(bih + cc);
    float4 biz = *reinterpret_cast<const float4*>(bih + F + cc);
    float4 bin = *reinterpret_cast<const float4*>(bih + 2 * F + cc);
    const float* bi_r = &bir.x;
    const float* bi_z = &biz.x;
    const float* bi_n = &bin.x;

    #pragma unroll
    for (int i = 0; i < 2; ++i) {
        int r = row0 + ty * 2 + i;
        const float* ghp = g_gh + (size_t)r * 3 * F;
        float4 ghr = *reinterpret_cast<const float4*>(ghp + cc);
        float4 ghz = *reinterpret_cast<const float4*>(ghp + F + cc);
        float4 ghn = *reinterpret_cast<const float4*>(ghp + 2 * F + cc);
        float4 h   = *reinterpret_cast<const float4*>(gf + (size_t)r * F + cc);

        float2 u;
        float gi_r[4], gi_z[4], gi_n[4];
        u = unpack2(acc[0][i][0]); gi_r[0] = u.x; gi_r[1] = u.y;
        u = unpack2(acc[0][i][1]); gi_r[2] = u.x; gi_r[3] = u.y;
        u = unpack2(acc[1][i][0]); gi_z[0] = u.x; gi_z[1] = u.y;
        u = unpack2(acc[1][i][1]); gi_z[2] = u.x; gi_z[3] = u.y;
        u = unpack2(acc[2][i][0]); gi_n[0] = u.x; gi_n[1] = u.y;
        u = unpack2(acc[2][i][1]); gi_n[2] = u.x; gi_n[3] = u.y;

        const float* ghr_p = &ghr.x;
        const float* ghz_p = &ghz.x;
        const float* ghn_p = &ghn.x;
        const float* h_p   = &h.x;

        float4 o;
        float* op = &o.x;
        #pragma unroll
        for (int k = 0; k < 4; ++k) {
            float rr = 0.5f * fast_tanh(0.5f * (gi_r[k] + bi_r[k] + ghr_p[k])) + 0.5f;
            float zz = 0.5f * fast_tanh(0.5f * (gi_z[k] + bi_z[k] + ghz_p[k])) + 0.5f;
            float nn = fast_tanh(fmaf(rr, ghn_p[k], gi_n[k] + bi_n[k]));
            op[k] = fmaf(1.f - zz, nn, zz * h_p[k]);
        }
        *reinterpret_cast<float4*>(out + (size_t)r * F + cc) = o;
    }
}

// ---------------- launch ----------------
extern "C" void kernel_launch(void* const* d_in, const int* in_sizes, int n_in,
                              void* d_out, int out_size)
{
    int o = (n_in >= 12) ? 1 : 0;
    const float* nf  = (const float*)d_in[0];
    const float* gf  = (const float*)d_in[1];
    const int*   seg = (const int*)  d_in[2];
    const float* lw  = (const float*)d_in[3 + o];
    const float* lb  = (const float*)d_in[4 + o];
    const float* pw  = (const float*)d_in[5 + o];
    const float* pb  = (const float*)d_in[6 + o];
    const float* wih = (const float*)d_in[7 + o];
    const float* whh = (const float*)d_in[8 + o];
    const float* bih = (const float*)d_in[9 + o];
    const float* bhh = (const float*)d_in[10 + o];
    float* out = (float*)d_out;
    int n_nodes = in_sizes[0] / F;

    fused_pool_gh_kernel<<<GH_BLOCKS + NG, 256>>>(nf, gf, lw, lb, whh, bhh, seg, n_nodes);
    proj_kernel<<<dim3(NG / 32, F / 64), 128>>>(pw, pb);
    gigru_kernel<<<dim3(NG / 16, F / 64), 128>>>(gf, wih, bih, out);
}